// round 6
// baseline (speedup 1.0000x reference)
#include <cuda_runtime.h>
#include <cuda_fp16.h>
#include <cstdint>

// ---------------------------------------------------------------------------
// Mipmapped texture sampling, fp16 pyramid, MLP-maximized sampler.
//   Pyramid channel-last (H,W,C) fp16: 32 B/texel (= one L2 sector).
//   K1: transpose (C,H,W) f32 -> (H,W,C) f16, 4 pixels/thread.
//   K2: levels 1..7 built directly from level 0.
//   K3: 2 lanes/query x 2 queries/thread; all 16 tap loads front-loaded.
// ---------------------------------------------------------------------------

#define NUM_LEVELS 8
#define BASE_W     512
#define CHANNELS   16

#define TOTAL_PIX  349520
#define L0_PIX     (512*512)
#define MIP_PIX    (TOTAL_PIX - L0_PIX)

__device__ __half g_pyr[(size_t)TOTAL_PIX * CHANNELS];   // ~11.2 MB

__device__ __forceinline__ int lvl_off(int l) {
    return (1048576 - (1048576 >> (2 * l))) / 3;
}

// ------------------------- Kernel 1: transpose + quantize ------------------
// 4 consecutive pixels per thread. Reads: per channel one float4 (lane-
// contiguous 512B/warp). Writes: 4 texels = 128B contiguous per thread.
__global__ void k_transpose(const float* __restrict__ tex) {
    int t = blockIdx.x * blockDim.x + threadIdx.x;     // 0..65535
    float4 v[CHANNELS];
#pragma unroll
    for (int c = 0; c < CHANNELS; ++c)
        v[c] = __ldg(&reinterpret_cast<const float4*>(tex + (size_t)c * L0_PIX)[t]);

    uint4* dst = reinterpret_cast<uint4*>(g_pyr + (size_t)t * 4 * CHANNELS);
#pragma unroll
    for (int px = 0; px < 4; ++px) {
        float f[CHANNELS];
#pragma unroll
        for (int c = 0; c < CHANNELS; ++c)
            f[c] = px == 0 ? v[c].x : px == 1 ? v[c].y : px == 2 ? v[c].z : v[c].w;
        __half2 h[8];
#pragma unroll
        for (int i = 0; i < 8; ++i)
            h[i] = __floats2half2_rn(f[2*i], f[2*i+1]);
        dst[px*2]   = *reinterpret_cast<uint4*>(&h[0]);
        dst[px*2+1] = *reinterpret_cast<uint4*>(&h[4]);
    }
}

// ------------------------- Kernel 2: build mips ----------------------------
__device__ __forceinline__ void load_texel16(const __half* ptr, float* f) {
    const uint4* p4 = reinterpret_cast<const uint4*>(ptr);
    uint4 a = p4[0], b = p4[1];
    const __half2* ha = reinterpret_cast<const __half2*>(&a);
    const __half2* hb = reinterpret_cast<const __half2*>(&b);
#pragma unroll
    for (int i = 0; i < 4; ++i) {
        float2 t = __half22float2(ha[i]);
        f[2*i] = t.x; f[2*i+1] = t.y;
    }
#pragma unroll
    for (int i = 0; i < 4; ++i) {
        float2 t = __half22float2(hb[i]);
        f[8+2*i] = t.x; f[8+2*i+1] = t.y;
    }
}

__global__ void k_mips() {
    int idx = blockIdx.x * blockDim.x + threadIdx.x;
    if (idx >= MIP_PIX) return;

    int l = 1, rem = idx;
#pragma unroll
    for (int i = 1; i < NUM_LEVELS; ++i) {
        int n = (BASE_W >> i) * (BASE_W >> i);
        if (rem < n) { l = i; break; }
        rem -= n;
    }
    int w = BASE_W >> l;
    int y = rem / w;
    int x = rem - y * w;
    float s = (float)(1 << l);

    float sy = fmaxf((y + 0.5f) * s - 0.5f, 0.0f);
    float sx = fmaxf((x + 0.5f) * s - 0.5f, 0.0f);
    int y0 = min((int)sy, BASE_W - 1);
    int x0 = min((int)sx, BASE_W - 1);
    int y1 = min(y0 + 1, BASE_W - 1);
    int x1 = min(x0 + 1, BASE_W - 1);
    float ty = sy - (float)y0;
    float tx = sx - (float)x0;

    float w00 = (1.0f - tx) * (1.0f - ty);
    float w01 = tx * (1.0f - ty);
    float w10 = (1.0f - tx) * ty;
    float w11 = tx * ty;

    float a[16], b[16], c[16], d[16];
    load_texel16(g_pyr + (size_t)(y0 * BASE_W + x0) * CHANNELS, a);
    load_texel16(g_pyr + (size_t)(y0 * BASE_W + x1) * CHANNELS, b);
    load_texel16(g_pyr + (size_t)(y1 * BASE_W + x0) * CHANNELS, c);
    load_texel16(g_pyr + (size_t)(y1 * BASE_W + x1) * CHANNELS, d);

    __half2 h[8];
#pragma unroll
    for (int i = 0; i < 8; ++i) {
        float r0 = a[2*i]   * w00 + b[2*i]   * w01 + c[2*i]   * w10 + d[2*i]   * w11;
        float r1 = a[2*i+1] * w00 + b[2*i+1] * w01 + c[2*i+1] * w10 + d[2*i+1] * w11;
        h[i] = __floats2half2_rn(r0, r1);
    }
    uint4* dst = reinterpret_cast<uint4*>(g_pyr + (size_t)(lvl_off(l) + rem) * CHANNELS);
    dst[0] = *reinterpret_cast<uint4*>(&h[0]);
    dst[1] = *reinterpret_cast<uint4*>(&h[4]);
}

// ------------------------- Kernel 3: sample --------------------------------
// 2 lanes per query (cg = 8-channel half-texel), 2 queries per thread.
// All 16 tap addresses computed first, then 16 loads issued back-to-back
// (MLP = 16), then the weight math.

struct TapSetup {
    const uint4* a0; const uint4* a1; const uint4* a2; const uint4* a3;  // l0 taps
    const uint4* b0; const uint4* b1; const uint4* b2; const uint4* b3;  // l1 taps
    float fx0, fy0, fx1, fy1, alpha;
};

__device__ __forceinline__ void setup_query(float2 uvq, float pq, int cg,
                                            TapSetup& S) {
    float lf = pq * (float)(NUM_LEVELS - 1);
    int l0 = min((int)lf, NUM_LEVELS - 1);
    int l1 = min(l0 + 1, NUM_LEVELS - 1);
    S.alpha = lf - (float)l0;

#pragma unroll
    for (int k = 0; k < 2; ++k) {
        int l = k ? l1 : l0;
        int w = BASE_W >> l;
        float fw = (float)(w - 1);
        float x = fminf(fmaxf(uvq.x * fw, 0.0f), fw);
        float y = fminf(fmaxf(uvq.y * fw, 0.0f), fw);
        int x0 = (int)x;
        int y0 = (int)y;
        int x1 = min(x0 + 1, w - 1);
        int y1 = min(y0 + 1, w - 1);
        const uint4* base = reinterpret_cast<const uint4*>(
            g_pyr + (size_t)lvl_off(l) * CHANNELS) + cg;
        const uint4* t0 = base + (size_t)(y0 * w + x0) * 2;
        const uint4* t1 = base + (size_t)(y0 * w + x1) * 2;
        const uint4* t2 = base + (size_t)(y1 * w + x0) * 2;
        const uint4* t3 = base + (size_t)(y1 * w + x1) * 2;
        if (k) {
            S.b0 = t0; S.b1 = t1; S.b2 = t2; S.b3 = t3;
            S.fx1 = x - (float)x0; S.fy1 = y - (float)y0;
        } else {
            S.a0 = t0; S.a1 = t1; S.a2 = t2; S.a3 = t3;
            S.fx0 = x - (float)x0; S.fy0 = y - (float)y0;
        }
    }
}

__device__ __forceinline__ void blend_store(const uint4* t, const TapSetup& S,
                                            float* out8) {
    float w00a = (1.0f - S.fx0) * (1.0f - S.fy0);
    float w01a = S.fx0 * (1.0f - S.fy0);
    float w10a = (1.0f - S.fx0) * S.fy0;
    float w11a = S.fx0 * S.fy0;
    float w00b = (1.0f - S.fx1) * (1.0f - S.fy1);
    float w01b = S.fx1 * (1.0f - S.fy1);
    float w10b = (1.0f - S.fx1) * S.fy1;
    float w11b = S.fx1 * S.fy1;
    float ia = 1.0f - S.alpha, al = S.alpha;

    const __half2* h0 = reinterpret_cast<const __half2*>(&t[0]);
    const __half2* h1 = reinterpret_cast<const __half2*>(&t[1]);
    const __half2* h2 = reinterpret_cast<const __half2*>(&t[2]);
    const __half2* h3 = reinterpret_cast<const __half2*>(&t[3]);
    const __half2* h4 = reinterpret_cast<const __half2*>(&t[4]);
    const __half2* h5 = reinterpret_cast<const __half2*>(&t[5]);
    const __half2* h6 = reinterpret_cast<const __half2*>(&t[6]);
    const __half2* h7 = reinterpret_cast<const __half2*>(&t[7]);

#pragma unroll
    for (int i = 0; i < 4; ++i) {
        float2 a0 = __half22float2(h0[i]);
        float2 a1 = __half22float2(h1[i]);
        float2 a2 = __half22float2(h2[i]);
        float2 a3 = __half22float2(h3[i]);
        float2 b0 = __half22float2(h4[i]);
        float2 b1 = __half22float2(h5[i]);
        float2 b2 = __half22float2(h6[i]);
        float2 b3 = __half22float2(h7[i]);
        float sa_x = a0.x*w00a + a1.x*w01a + a2.x*w10a + a3.x*w11a;
        float sa_y = a0.y*w00a + a1.y*w01a + a2.y*w10a + a3.y*w11a;
        float sb_x = b0.x*w00b + b1.x*w01b + b2.x*w10b + b3.x*w11b;
        float sb_y = b0.y*w00b + b1.y*w01b + b2.y*w10b + b3.y*w11b;
        out8[2*i]   = sa_x * ia + sb_x * al;
        out8[2*i+1] = sa_y * ia + sb_y * al;
    }
}

__global__ void __launch_bounds__(256)
k_sample(const float2* __restrict__ uv,
         const float* __restrict__ p,
         float* __restrict__ out, int n) {
    int tid = blockIdx.x * blockDim.x + threadIdx.x;
    int half = n >> 1;
    int q = tid >> 1;
    if (q >= half) return;
    int cg = tid & 1;
    int q2 = q + half;

    float2 uvA = __ldg(&uv[q]);
    float  pA  = __ldg(&p[q]);
    float2 uvB = __ldg(&uv[q2]);
    float  pB  = __ldg(&p[q2]);

    TapSetup SA, SB;
    setup_query(uvA, pA, cg, SA);
    setup_query(uvB, pB, cg, SB);

    // ---- front-load all 16 taps ----
    uint4 tA[8], tB[8];
    tA[0] = *SA.a0; tA[1] = *SA.a1; tA[2] = *SA.a2; tA[3] = *SA.a3;
    tA[4] = *SA.b0; tA[5] = *SA.b1; tA[6] = *SA.b2; tA[7] = *SA.b3;
    tB[0] = *SB.a0; tB[1] = *SB.a1; tB[2] = *SB.a2; tB[3] = *SB.a3;
    tB[4] = *SB.b0; tB[5] = *SB.b1; tB[6] = *SB.b2; tB[7] = *SB.b3;

    float rA[8], rB[8];
    blend_store(tA, SA, rA);
    blend_store(tB, SB, rB);

    float4* dstA = reinterpret_cast<float4*>(out + (size_t)q  * CHANNELS) + cg * 2;
    float4* dstB = reinterpret_cast<float4*>(out + (size_t)q2 * CHANNELS) + cg * 2;
    dstA[0] = make_float4(rA[0], rA[1], rA[2], rA[3]);
    dstA[1] = make_float4(rA[4], rA[5], rA[6], rA[7]);
    dstB[0] = make_float4(rB[0], rB[1], rB[2], rB[3]);
    dstB[1] = make_float4(rB[4], rB[5], rB[6], rB[7]);
}

// odd-n tail (n/2*2 < n): handle last query with the simple path
__global__ void k_sample_tail(const float2* __restrict__ uv,
                              const float* __restrict__ p,
                              float* __restrict__ out, int q) {
    int cg = threadIdx.x & 1;
    if (threadIdx.x >= 2) return;
    TapSetup S;
    setup_query(__ldg(&uv[q]), __ldg(&p[q]), cg, S);
    uint4 t[8];
    t[0] = *S.a0; t[1] = *S.a1; t[2] = *S.a2; t[3] = *S.a3;
    t[4] = *S.b0; t[5] = *S.b1; t[6] = *S.b2; t[7] = *S.b3;
    float r[8];
    blend_store(t, S, r);
    float4* dst = reinterpret_cast<float4*>(out + (size_t)q * CHANNELS) + cg * 2;
    dst[0] = make_float4(r[0], r[1], r[2], r[3]);
    dst[1] = make_float4(r[4], r[5], r[6], r[7]);
}

// ---------------------------------------------------------------------------
extern "C" void kernel_launch(void* const* d_in, const int* in_sizes, int n_in,
                              void* d_out, int out_size) {
    const float* uv  = (const float*)d_in[0];
    const float* p   = (const float*)d_in[1];
    const float* tex = (const float*)d_in[2];
    float* out = (float*)d_out;
    int n = in_sizes[1];

    k_transpose<<<L0_PIX / 4 / 256, 256>>>(tex);
    k_mips<<<(MIP_PIX + 255) / 256, 256>>>();

    int half = n >> 1;
    int threads = half * 2;                    // 2 lanes x half query-pairs
    k_sample<<<(threads + 255) / 256, 256>>>(
        (const float2*)uv, p, out, n);
    if (n & 1)
        k_sample_tail<<<1, 32>>>((const float2*)uv, p, out, n - 1);
}

// round 8
// speedup vs baseline: 1.0879x; 1.0879x over previous
#include <cuda_runtime.h>
#include <cuda_fp16.h>
#include <cstdint>

// ---------------------------------------------------------------------------
// Mipmapped texture sampling, fp16 pyramid.
//   K1: transpose (C,H,W) f32 -> (H,W,C) f16 level 0 (1 px/thread).
//   K2: levels 1..7 from level 0.
//   K3: 2 lanes/query, 8 front-loaded taps; levels 4..7 (43.5 KB) staged in
//       static shared memory, tap loads via generic pointers (smem or gmem
//       chosen per tap). Halves the L1tex gmem wavefront load.
// ---------------------------------------------------------------------------

#define NUM_LEVELS 8
#define BASE_W     512
#define CHANNELS   16

#define TOTAL_PIX  349520
#define L0_PIX     (512*512)
#define MIP_PIX    (TOTAL_PIX - L0_PIX)

#define SMEM_LVL   4                       // levels >= this live in smem
#define SMEM_PIX0  348160                  // lvl_off(4)
#define SMEM_PIX   (TOTAL_PIX - SMEM_PIX0) // 1360 texels
#define SMEM_HALFS (SMEM_PIX * CHANNELS)   // 21760 halves = 43520 B
#define SMEM_U4    (SMEM_HALFS / 8)        // 2720 uint4 copies

__device__ __half g_pyr[(size_t)TOTAL_PIX * CHANNELS];   // ~11.2 MB

__device__ __forceinline__ int lvl_off(int l) {
    return (1048576 - (1048576 >> (2 * l))) / 3;
}

// ------------------------- Kernel 1: transpose + quantize ------------------
__global__ void k_transpose(const float* __restrict__ tex) {
    int pix = blockIdx.x * blockDim.x + threadIdx.x;   // 0..262143
    float v[CHANNELS];
#pragma unroll
    for (int c = 0; c < CHANNELS; ++c)
        v[c] = __ldg(&tex[(size_t)c * L0_PIX + pix]);
    __half2 h[8];
#pragma unroll
    for (int i = 0; i < 8; ++i)
        h[i] = __floats2half2_rn(v[2*i], v[2*i+1]);
    uint4* dst = reinterpret_cast<uint4*>(g_pyr + (size_t)pix * CHANNELS);
    dst[0] = *reinterpret_cast<uint4*>(&h[0]);
    dst[1] = *reinterpret_cast<uint4*>(&h[4]);
}

// ------------------------- Kernel 2: build mips ----------------------------
__device__ __forceinline__ void load_texel16(const __half* ptr, float* f) {
    const uint4* p4 = reinterpret_cast<const uint4*>(ptr);
    uint4 a = p4[0], b = p4[1];
    const __half2* ha = reinterpret_cast<const __half2*>(&a);
    const __half2* hb = reinterpret_cast<const __half2*>(&b);
#pragma unroll
    for (int i = 0; i < 4; ++i) {
        float2 t = __half22float2(ha[i]);
        f[2*i] = t.x; f[2*i+1] = t.y;
    }
#pragma unroll
    for (int i = 0; i < 4; ++i) {
        float2 t = __half22float2(hb[i]);
        f[8+2*i] = t.x; f[8+2*i+1] = t.y;
    }
}

__global__ void k_mips() {
    int idx = blockIdx.x * blockDim.x + threadIdx.x;
    if (idx >= MIP_PIX) return;

    int l = 1, rem = idx;
#pragma unroll
    for (int i = 1; i < NUM_LEVELS; ++i) {
        int n = (BASE_W >> i) * (BASE_W >> i);
        if (rem < n) { l = i; break; }
        rem -= n;
    }
    int w = BASE_W >> l;
    int y = rem / w;
    int x = rem - y * w;
    float s = (float)(1 << l);

    float sy = fmaxf((y + 0.5f) * s - 0.5f, 0.0f);
    float sx = fmaxf((x + 0.5f) * s - 0.5f, 0.0f);
    int y0 = min((int)sy, BASE_W - 1);
    int x0 = min((int)sx, BASE_W - 1);
    int y1 = min(y0 + 1, BASE_W - 1);
    int x1 = min(x0 + 1, BASE_W - 1);
    float ty = sy - (float)y0;
    float tx = sx - (float)x0;

    float w00 = (1.0f - tx) * (1.0f - ty);
    float w01 = tx * (1.0f - ty);
    float w10 = (1.0f - tx) * ty;
    float w11 = tx * ty;

    float a[16], b[16], c[16], d[16];
    load_texel16(g_pyr + (size_t)(y0 * BASE_W + x0) * CHANNELS, a);
    load_texel16(g_pyr + (size_t)(y0 * BASE_W + x1) * CHANNELS, b);
    load_texel16(g_pyr + (size_t)(y1 * BASE_W + x0) * CHANNELS, c);
    load_texel16(g_pyr + (size_t)(y1 * BASE_W + x1) * CHANNELS, d);

    __half2 h[8];
#pragma unroll
    for (int i = 0; i < 8; ++i) {
        float r0 = a[2*i]   * w00 + b[2*i]   * w01 + c[2*i]   * w10 + d[2*i]   * w11;
        float r1 = a[2*i+1] * w00 + b[2*i+1] * w01 + c[2*i+1] * w10 + d[2*i+1] * w11;
        h[i] = __floats2half2_rn(r0, r1);
    }
    uint4* dst = reinterpret_cast<uint4*>(g_pyr + (size_t)(lvl_off(l) + rem) * CHANNELS);
    dst[0] = *reinterpret_cast<uint4*>(&h[0]);
    dst[1] = *reinterpret_cast<uint4*>(&h[4]);
}

// ------------------------- Kernel 3: sample --------------------------------
// 2 lanes/query (cg picks the 16 B half-texel). Levels >= SMEM_LVL are read
// from a block-local shared copy; the per-tap pointer is generic.

struct TapSetup {
    const uint4* t[8];                 // 4 taps level l0, 4 taps level l1
    float fx0, fy0, fx1, fy1, alpha;
};

__device__ __forceinline__ void setup_query(float2 uvq, float pq, int cg,
                                            const __half* s_hi, TapSetup& S) {
    float lf = pq * (float)(NUM_LEVELS - 1);
    int l0 = min((int)lf, NUM_LEVELS - 1);
    int l1 = min(l0 + 1, NUM_LEVELS - 1);
    S.alpha = lf - (float)l0;

#pragma unroll
    for (int k = 0; k < 2; ++k) {
        int l = k ? l1 : l0;
        int w = BASE_W >> l;
        float fw = (float)(w - 1);
        float x = fminf(fmaxf(uvq.x * fw, 0.0f), fw);
        float y = fminf(fmaxf(uvq.y * fw, 0.0f), fw);
        int x0 = (int)x;
        int y0 = (int)y;
        int x1 = min(x0 + 1, w - 1);
        int y1 = min(y0 + 1, w - 1);

        // generic base: smem copy for small levels, gmem otherwise
        const __half* lev = (l >= SMEM_LVL)
            ? (s_hi + (size_t)(lvl_off(l) - SMEM_PIX0) * CHANNELS)
            : (g_pyr + (size_t)lvl_off(l) * CHANNELS);
        const uint4* base = reinterpret_cast<const uint4*>(lev) + cg;

        S.t[k*4+0] = base + (size_t)(y0 * w + x0) * 2;
        S.t[k*4+1] = base + (size_t)(y0 * w + x1) * 2;
        S.t[k*4+2] = base + (size_t)(y1 * w + x0) * 2;
        S.t[k*4+3] = base + (size_t)(y1 * w + x1) * 2;
        if (k) { S.fx1 = x - (float)x0; S.fy1 = y - (float)y0; }
        else   { S.fx0 = x - (float)x0; S.fy0 = y - (float)y0; }
    }
}

__global__ void __launch_bounds__(1024, 1)
k_sample(const float2* __restrict__ uv,
         const float* __restrict__ p,
         float* __restrict__ out, int n) {
    __shared__ __half s_hi[SMEM_HALFS];    // 43520 B: levels 4..7

    // stage small levels into smem (sequential, L2-hot)
    {
        const uint4* src = reinterpret_cast<const uint4*>(
            g_pyr + (size_t)SMEM_PIX0 * CHANNELS);
        uint4* dst = reinterpret_cast<uint4*>(s_hi);
        for (int i = threadIdx.x; i < SMEM_U4; i += blockDim.x)
            dst[i] = src[i];
    }
    __syncthreads();

    int tid = blockIdx.x * blockDim.x + threadIdx.x;
    int q = tid >> 1;
    if (q >= n) return;
    int cg = tid & 1;

    float2 uvq = __ldg(&uv[q]);
    float  pq  = __ldg(&p[q]);

    TapSetup S;
    setup_query(uvq, pq, cg, s_hi, S);

    // front-load all 8 taps (generic loads; MLP=8)
    uint4 t0 = *S.t[0], t1 = *S.t[1], t2 = *S.t[2], t3 = *S.t[3];
    uint4 t4 = *S.t[4], t5 = *S.t[5], t6 = *S.t[6], t7 = *S.t[7];

    float w00a = (1.0f - S.fx0) * (1.0f - S.fy0);
    float w01a = S.fx0 * (1.0f - S.fy0);
    float w10a = (1.0f - S.fx0) * S.fy0;
    float w11a = S.fx0 * S.fy0;
    float w00b = (1.0f - S.fx1) * (1.0f - S.fy1);
    float w01b = S.fx1 * (1.0f - S.fy1);
    float w10b = (1.0f - S.fx1) * S.fy1;
    float w11b = S.fx1 * S.fy1;
    float ia = 1.0f - S.alpha, al = S.alpha;

    const __half2* h0 = reinterpret_cast<const __half2*>(&t0);
    const __half2* h1 = reinterpret_cast<const __half2*>(&t1);
    const __half2* h2 = reinterpret_cast<const __half2*>(&t2);
    const __half2* h3 = reinterpret_cast<const __half2*>(&t3);
    const __half2* h4 = reinterpret_cast<const __half2*>(&t4);
    const __half2* h5 = reinterpret_cast<const __half2*>(&t5);
    const __half2* h6 = reinterpret_cast<const __half2*>(&t6);
    const __half2* h7 = reinterpret_cast<const __half2*>(&t7);

    float r[8];
#pragma unroll
    for (int i = 0; i < 4; ++i) {
        float2 a0 = __half22float2(h0[i]);
        float2 a1 = __half22float2(h1[i]);
        float2 a2 = __half22float2(h2[i]);
        float2 a3 = __half22float2(h3[i]);
        float2 b0 = __half22float2(h4[i]);
        float2 b1 = __half22float2(h5[i]);
        float2 b2 = __half22float2(h6[i]);
        float2 b3 = __half22float2(h7[i]);
        float sa_x = a0.x*w00a + a1.x*w01a + a2.x*w10a + a3.x*w11a;
        float sa_y = a0.y*w00a + a1.y*w01a + a2.y*w10a + a3.y*w11a;
        float sb_x = b0.x*w00b + b1.x*w01b + b2.x*w10b + b3.x*w11b;
        float sb_y = b0.y*w00b + b1.y*w01b + b2.y*w10b + b3.y*w11b;
        r[2*i]   = sa_x * ia + sb_x * al;
        r[2*i+1] = sa_y * ia + sb_y * al;
    }

    float4* dst = reinterpret_cast<float4*>(out + (size_t)q * CHANNELS) + cg * 2;
    dst[0] = make_float4(r[0], r[1], r[2], r[3]);
    dst[1] = make_float4(r[4], r[5], r[6], r[7]);
}

// ---------------------------------------------------------------------------
extern "C" void kernel_launch(void* const* d_in, const int* in_sizes, int n_in,
                              void* d_out, int out_size) {
    const float* uv  = (const float*)d_in[0];
    const float* p   = (const float*)d_in[1];
    const float* tex = (const float*)d_in[2];
    float* out = (float*)d_out;
    int n = in_sizes[1];

    k_transpose<<<L0_PIX / 256, 256>>>(tex);
    k_mips<<<(MIP_PIX + 255) / 256, 256>>>();

    int threads = n * 2;
    k_sample<<<(threads + 1023) / 1024, 1024>>>(
        (const float2*)uv, p, out, n);
}

// round 9
// speedup vs baseline: 1.5977x; 1.4686x over previous
#include <cuda_runtime.h>
#include <cuda_fp16.h>
#include <cstdint>

// ---------------------------------------------------------------------------
// Mipmapped texture sampling, fp16 pyramid, x-pair-merged sampler.
//   Pyramid channel-last (H,W,C) fp16: 32 B/texel.
//   K1: transpose (C,H,W) f32 -> (H,W,C) f16 (round-3 version).
//   K2: levels 1..7 from level 0.
//   K3: 4 lanes/query: lane = (xsel, channel-half). Each tap row (y, level)
//       is ONE instruction covering 64 B contiguous (both x taps) -> x-pair
//       lines merge into one L1tex wavefront 75% of the time. x-blend via
//       one shfl_xor reduction.
// ---------------------------------------------------------------------------

#define NUM_LEVELS 8
#define BASE_W     512
#define CHANNELS   16

#define TOTAL_PIX  349520
#define L0_PIX     (512*512)
#define MIP_PIX    (TOTAL_PIX - L0_PIX)

__device__ __half g_pyr[(size_t)TOTAL_PIX * CHANNELS];   // ~11.2 MB

__device__ __forceinline__ int lvl_off(int l) {
    return (1048576 - (1048576 >> (2 * l))) / 3;
}

// ------------------------- Kernel 1: transpose + quantize ------------------
__global__ void k_transpose(const float* __restrict__ tex) {
    int pix = blockIdx.x * blockDim.x + threadIdx.x;   // 0..262143
    float v[CHANNELS];
#pragma unroll
    for (int c = 0; c < CHANNELS; ++c)
        v[c] = __ldg(&tex[(size_t)c * L0_PIX + pix]);
    __half2 h[8];
#pragma unroll
    for (int i = 0; i < 8; ++i)
        h[i] = __floats2half2_rn(v[2*i], v[2*i+1]);
    uint4* dst = reinterpret_cast<uint4*>(g_pyr + (size_t)pix * CHANNELS);
    dst[0] = *reinterpret_cast<uint4*>(&h[0]);
    dst[1] = *reinterpret_cast<uint4*>(&h[4]);
}

// ------------------------- Kernel 2: build mips ----------------------------
__device__ __forceinline__ void load_texel16(const __half* ptr, float* f) {
    const uint4* p4 = reinterpret_cast<const uint4*>(ptr);
    uint4 a = p4[0], b = p4[1];
    const __half2* ha = reinterpret_cast<const __half2*>(&a);
    const __half2* hb = reinterpret_cast<const __half2*>(&b);
#pragma unroll
    for (int i = 0; i < 4; ++i) {
        float2 t = __half22float2(ha[i]);
        f[2*i] = t.x; f[2*i+1] = t.y;
    }
#pragma unroll
    for (int i = 0; i < 4; ++i) {
        float2 t = __half22float2(hb[i]);
        f[8+2*i] = t.x; f[8+2*i+1] = t.y;
    }
}

__global__ void k_mips() {
    int idx = blockIdx.x * blockDim.x + threadIdx.x;
    if (idx >= MIP_PIX) return;

    int l = 1, rem = idx;
#pragma unroll
    for (int i = 1; i < NUM_LEVELS; ++i) {
        int n = (BASE_W >> i) * (BASE_W >> i);
        if (rem < n) { l = i; break; }
        rem -= n;
    }
    int w = BASE_W >> l;
    int y = rem / w;
    int x = rem - y * w;
    float s = (float)(1 << l);

    float sy = fmaxf((y + 0.5f) * s - 0.5f, 0.0f);
    float sx = fmaxf((x + 0.5f) * s - 0.5f, 0.0f);
    int y0 = min((int)sy, BASE_W - 1);
    int x0 = min((int)sx, BASE_W - 1);
    int y1 = min(y0 + 1, BASE_W - 1);
    int x1 = min(x0 + 1, BASE_W - 1);
    float ty = sy - (float)y0;
    float tx = sx - (float)x0;

    float w00 = (1.0f - tx) * (1.0f - ty);
    float w01 = tx * (1.0f - ty);
    float w10 = (1.0f - tx) * ty;
    float w11 = tx * ty;

    float a[16], b[16], c[16], d[16];
    load_texel16(g_pyr + (size_t)(y0 * BASE_W + x0) * CHANNELS, a);
    load_texel16(g_pyr + (size_t)(y0 * BASE_W + x1) * CHANNELS, b);
    load_texel16(g_pyr + (size_t)(y1 * BASE_W + x0) * CHANNELS, c);
    load_texel16(g_pyr + (size_t)(y1 * BASE_W + x1) * CHANNELS, d);

    __half2 h[8];
#pragma unroll
    for (int i = 0; i < 8; ++i) {
        float r0 = a[2*i]   * w00 + b[2*i]   * w01 + c[2*i]   * w10 + d[2*i]   * w11;
        float r1 = a[2*i+1] * w00 + b[2*i+1] * w01 + c[2*i+1] * w10 + d[2*i+1] * w11;
        h[i] = __floats2half2_rn(r0, r1);
    }
    uint4* dst = reinterpret_cast<uint4*>(g_pyr + (size_t)(lvl_off(l) + rem) * CHANNELS);
    dst[0] = *reinterpret_cast<uint4*>(&h[0]);
    dst[1] = *reinterpret_cast<uint4*>(&h[4]);
}

// ------------------------- Kernel 3: sample --------------------------------
// 4 lanes per query. lane bit0 = xsel (x0/x1 tap), bit1 = cg (channel half).
// Per lane: 4 loads (y0/y1 rows x l0/l1 levels). y-lerp + level-lerp in-lane
// with x-weight folded in; then shfl_xor(1) sums the two x taps.
__global__ void __launch_bounds__(256)
k_sample(const float2* __restrict__ uv,
         const float* __restrict__ p,
         float* __restrict__ out, int n) {
    int tid = blockIdx.x * blockDim.x + threadIdx.x;
    int q = tid >> 2;
    bool valid = (q < n);
    int qc = valid ? q : (n - 1);          // clamp; keep full warp for shfl
    int lane = tid & 3;
    int xsel = lane & 1;
    int cg   = lane >> 1;

    float2 uvq = __ldg(&uv[qc]);
    float lf = __ldg(&p[qc]) * (float)(NUM_LEVELS - 1);
    int l0 = min((int)lf, NUM_LEVELS - 1);
    int l1 = min(l0 + 1, NUM_LEVELS - 1);
    float alpha = lf - (float)l0;

    const uint4* pA[2];
    const uint4* pB[2];
    float wx[2], fyv[2];
#pragma unroll
    for (int k = 0; k < 2; ++k) {
        int l = k ? l1 : l0;
        int w = BASE_W >> l;
        float fw = (float)(w - 1);
        float x = fminf(fmaxf(uvq.x * fw, 0.0f), fw);
        float y = fminf(fmaxf(uvq.y * fw, 0.0f), fw);
        int x0 = (int)x;
        int y0 = (int)y;
        int x1 = min(x0 + 1, w - 1);
        int y1 = min(y0 + 1, w - 1);
        float fx = x - (float)x0;
        int xs = xsel ? x1 : x0;
        const uint4* base = reinterpret_cast<const uint4*>(
            g_pyr + (size_t)lvl_off(l) * CHANNELS) + cg;
        pA[k] = base + (size_t)(y0 * w + xs) * 2;   // row y0
        pB[k] = base + (size_t)(y1 * w + xs) * 2;   // row y1
        wx[k]  = xsel ? fx : 1.0f - fx;
        fyv[k] = y - (float)y0;
    }

    // 4 front-loaded taps (16 B each); x-pair lanes hit the same 64 B span.
    uint4 a0 = __ldg(pA[0]);
    uint4 b0 = __ldg(pB[0]);
    uint4 a1 = __ldg(pA[1]);
    uint4 b1 = __ldg(pB[1]);

    float w0 = (1.0f - alpha) * wx[0];
    float w1 = alpha * wx[1];
    float fy0 = fyv[0], fy1 = fyv[1];

    const __half2* hA0 = reinterpret_cast<const __half2*>(&a0);
    const __half2* hB0 = reinterpret_cast<const __half2*>(&b0);
    const __half2* hA1 = reinterpret_cast<const __half2*>(&a1);
    const __half2* hB1 = reinterpret_cast<const __half2*>(&b1);

    float s[8];
#pragma unroll
    for (int i = 0; i < 4; ++i) {
        float2 fa0 = __half22float2(hA0[i]);
        float2 fb0 = __half22float2(hB0[i]);
        float2 fa1 = __half22float2(hA1[i]);
        float2 fb1 = __half22float2(hB1[i]);
        float v0x = fa0.x + fy0 * (fb0.x - fa0.x);
        float v0y = fa0.y + fy0 * (fb0.y - fa0.y);
        float v1x = fa1.x + fy1 * (fb1.x - fa1.x);
        float v1y = fa1.y + fy1 * (fb1.y - fa1.y);
        s[2*i]   = v0x * w0 + v1x * w1;
        s[2*i+1] = v0y * w0 + v1y * w1;
    }

    // sum the two x taps (partner lane differs in bit 0)
#pragma unroll
    for (int i = 0; i < 8; ++i)
        s[i] += __shfl_xor_sync(0xFFFFFFFFu, s[i], 1);

    if (valid) {
        // lane = xsel + 2*cg -> float4 slot `lane` of the 16-channel output
        float4 o = xsel ? make_float4(s[4], s[5], s[6], s[7])
                        : make_float4(s[0], s[1], s[2], s[3]);
        reinterpret_cast<float4*>(out + (size_t)q * CHANNELS)[lane] = o;
    }
}

// ---------------------------------------------------------------------------
extern "C" void kernel_launch(void* const* d_in, const int* in_sizes, int n_in,
                              void* d_out, int out_size) {
    const float* uv  = (const float*)d_in[0];
    const float* p   = (const float*)d_in[1];
    const float* tex = (const float*)d_in[2];
    float* out = (float*)d_out;
    int n = in_sizes[1];

    k_transpose<<<L0_PIX / 256, 256>>>(tex);
    k_mips<<<(MIP_PIX + 255) / 256, 256>>>();

    int threads = n * 4;
    k_sample<<<(threads + 255) / 256, 256>>>(
        (const float2*)uv, p, out, n);
}